// round 7
// baseline (speedup 1.0000x reference)
#include <cuda_runtime.h>
#include <cuda_bf16.h>

// ---------------------------------------------------------------------------
// Problem constants
// ---------------------------------------------------------------------------
#define NROWS   4096
#define DIN     512
#define H1DIM   2048
#define H2DIM   128
#define DSC     512       // score dim
#define HEADC   2002
#define CUT0    2000
#define CUT1    10000
#define C0N     8000
#define C1N     40000
#define K0      128       // tail0 hidden
#define K1      32        // tail1 hidden

#define HEAD_TILES  32    // ceil(2002/64)
#define T0_TILES    125   // 8000/64
#define T1_TILES    625   // 40000/64

// ---------------------------------------------------------------------------
// Scratch (device globals; allocation-free)
// ---------------------------------------------------------------------------
__device__ float g_h1[NROWS * H1DIM];
__device__ float g_h2[NROWS * H2DIM];
__device__ float g_score[NROWS * DSC];
__device__ float g_h0[NROWS * K0];
__device__ float g_h1t[NROWS * K1];
__device__ float g_headPart[NROWS * HEAD_TILES];
__device__ float g_t0Part[NROWS * T0_TILES];
__device__ float g_t1Part[NROWS * T1_TILES];
__device__ float g_gHT[NROWS];
__device__ float g_gC0[NROWS];
__device__ float g_gC1[NROWS];
__device__ float g_gT0[NROWS];
__device__ float g_gT1[NROWS];
__device__ int   g_t_is64;

// ---------------------------------------------------------------------------
// int64/int32 target detection (JAX may demote int64 -> int32 without x64)
// ---------------------------------------------------------------------------
__global__ void detect_t_kernel(const unsigned int* __restrict__ tw) {
    if (threadIdx.x == 0) {
        int is64 = 1;
        for (int i = 0; i < 64; i++) {
            if (tw[2 * i + 1] != 0u) { is64 = 0; break; }
        }
        g_t_is64 = is64;
    }
}

__device__ __forceinline__ long long load_t(const void* t, int i) {
    if (g_t_is64) return ((const long long*)t)[i];
    return (long long)((const int*)t)[i];
}

// ---------------------------------------------------------------------------
// Generic tiled GEMM-NT:  C[m,n] = act( sum_k A[m,k]*B[n,k] + bias[n] )
// A: [M,K] row-major, B: [N,K] row-major (weight layout), C: [M,N]
// BM=BN=64, BK=16, 256 threads, 4x4 per-thread tile.
// M must be a multiple of 64 and K a multiple of 16 (true for all calls).
// ---------------------------------------------------------------------------
template<bool RELU, bool BIAS>
__global__ __launch_bounds__(256)
void gemm_nt_kernel(const float* __restrict__ A, const float* __restrict__ B,
                    const float* __restrict__ bias, float* __restrict__ C,
                    int M, int N, int K)
{
    __shared__ float As[16][68];
    __shared__ float Bs[16][68];

    const int tid = threadIdx.x;
    const int tx = tid & 15;
    const int ty = tid >> 4;
    const int m0 = blockIdx.y * 64;
    const int n0 = blockIdx.x * 64;

    const int lr = tid >> 2;          // 0..63
    const int lc = (tid & 3) * 4;     // 0,4,8,12

    const float* Aload = A + (long long)(m0 + lr) * K;
    const bool bvalid = (n0 + lr) < N;
    const float* Bload = B + (long long)(n0 + lr) * K;

    float acc[4][4];
#pragma unroll
    for (int i = 0; i < 4; i++)
#pragma unroll
        for (int j = 0; j < 4; j++) acc[i][j] = 0.f;

    for (int k0 = 0; k0 < K; k0 += 16) {
        float4 av = *(const float4*)(Aload + k0 + lc);
        float4 bv = bvalid ? *(const float4*)(Bload + k0 + lc)
                           : make_float4(0.f, 0.f, 0.f, 0.f);
        As[lc + 0][lr] = av.x; As[lc + 1][lr] = av.y;
        As[lc + 2][lr] = av.z; As[lc + 3][lr] = av.w;
        Bs[lc + 0][lr] = bv.x; Bs[lc + 1][lr] = bv.y;
        Bs[lc + 2][lr] = bv.z; Bs[lc + 3][lr] = bv.w;
        __syncthreads();
#pragma unroll
        for (int k = 0; k < 16; k++) {
            float4 a = *(const float4*)(&As[k][ty * 4]);
            float4 b = *(const float4*)(&Bs[k][tx * 4]);
            float ar[4] = {a.x, a.y, a.z, a.w};
            float br[4] = {b.x, b.y, b.z, b.w};
#pragma unroll
            for (int i = 0; i < 4; i++)
#pragma unroll
                for (int j = 0; j < 4; j++)
                    acc[i][j] = fmaf(ar[i], br[j], acc[i][j]);
        }
        __syncthreads();
    }

#pragma unroll
    for (int i = 0; i < 4; i++) {
        int m = m0 + ty * 4 + i;
#pragma unroll
        for (int j = 0; j < 4; j++) {
            int n = n0 + tx * 4 + j;
            if (n < N) {
                float v = acc[i][j];
                if (BIAS) v += bias[n];
                if (RELU) v = fmaxf(v, 0.f);
                C[(long long)m * N + n] = v;
            }
        }
    }
}

// ---------------------------------------------------------------------------
// Fused GEMM + exp + per-row partial sum over one 64-class tile.
// part[m * nTiles + tileIdx] = sum_{n in tile} exp(logit(m,n))
// Logits are tiny (|x| << 1), so no max-subtraction is needed.
// ---------------------------------------------------------------------------
template<bool BIAS>
__global__ __launch_bounds__(256)
void sumexp_kernel(const float* __restrict__ A, const float* __restrict__ B,
                   const float* __restrict__ bias, float* __restrict__ part,
                   int M, int C, int K, int nTiles)
{
    __shared__ float As[16][68];
    __shared__ float Bs[16][68];

    const int tid = threadIdx.x;
    const int tx = tid & 15;
    const int ty = tid >> 4;
    const int m0 = blockIdx.y * 64;
    const int n0 = blockIdx.x * 64;

    const int lr = tid >> 2;
    const int lc = (tid & 3) * 4;

    const float* Aload = A + (long long)(m0 + lr) * K;
    const bool bvalid = (n0 + lr) < C;
    const float* Bload = B + (long long)(n0 + lr) * K;

    float acc[4][4];
#pragma unroll
    for (int i = 0; i < 4; i++)
#pragma unroll
        for (int j = 0; j < 4; j++) acc[i][j] = 0.f;

    for (int k0 = 0; k0 < K; k0 += 16) {
        float4 av = *(const float4*)(Aload + k0 + lc);
        float4 bv = bvalid ? *(const float4*)(Bload + k0 + lc)
                           : make_float4(0.f, 0.f, 0.f, 0.f);
        As[lc + 0][lr] = av.x; As[lc + 1][lr] = av.y;
        As[lc + 2][lr] = av.z; As[lc + 3][lr] = av.w;
        Bs[lc + 0][lr] = bv.x; Bs[lc + 1][lr] = bv.y;
        Bs[lc + 2][lr] = bv.z; Bs[lc + 3][lr] = bv.w;
        __syncthreads();
#pragma unroll
        for (int k = 0; k < 16; k++) {
            float4 a = *(const float4*)(&As[k][ty * 4]);
            float4 b = *(const float4*)(&Bs[k][tx * 4]);
            float ar[4] = {a.x, a.y, a.z, a.w};
            float br[4] = {b.x, b.y, b.z, b.w};
#pragma unroll
            for (int i = 0; i < 4; i++)
#pragma unroll
                for (int j = 0; j < 4; j++)
                    acc[i][j] = fmaf(ar[i], br[j], acc[i][j]);
        }
        __syncthreads();
    }

#pragma unroll
    for (int i = 0; i < 4; i++) {
        float s = 0.f;
#pragma unroll
        for (int j = 0; j < 4; j++) {
            int n = n0 + tx * 4 + j;
            if (n < C) {
                float v = acc[i][j];
                if (BIAS) v += bias[n];
                s += __expf(v);
            }
        }
        // reduce across the 16 tx lanes (lane = (ty&1)*16 + tx)
#pragma unroll
        for (int off = 8; off > 0; off >>= 1)
            s += __shfl_xor_sync(0xffffffffu, s, off);
        if (tx == 0)
            part[(long long)(m0 + ty * 4 + i) * nTiles + blockIdx.x] = s;
    }
}

// ---------------------------------------------------------------------------
// Gathered logits: 5 dot products per row (one warp each).
// ---------------------------------------------------------------------------
__device__ __forceinline__ float warp_dot(const float* __restrict__ a,
                                          const float* __restrict__ w,
                                          int K, int lane)
{
    float s = 0.f;
    for (int k = lane; k < K; k += 32) s = fmaf(a[k], w[k], s);
#pragma unroll
    for (int off = 16; off > 0; off >>= 1)
        s += __shfl_xor_sync(0xffffffffu, s, off);
    return s;
}

__global__ void gather_kernel(const float* __restrict__ score,
                              const float* __restrict__ h0,
                              const float* __restrict__ h1t,
                              const float* __restrict__ headW,
                              const float* __restrict__ headB,
                              const float* __restrict__ t0b,
                              const float* __restrict__ t1b,
                              const void* __restrict__ t)
{
    int row = blockIdx.x;
    int w = threadIdx.x >> 5;
    int lane = threadIdx.x & 31;
    long long tv = load_t(t, row);

    if (w == 0) {
        long long c = tv; if (c < 0) c = 0; if (c > CUT0 - 1) c = CUT0 - 1;
        int idx = (int)c;
        float s = warp_dot(score + (long long)row * DSC,
                           headW + (long long)idx * DIN, DIN, lane);
        if (lane == 0) g_gHT[row] = s + headB[idx];
    } else if (w == 1) {
        float s = warp_dot(score + (long long)row * DSC,
                           headW + (long long)CUT0 * DIN, DIN, lane);
        if (lane == 0) g_gC0[row] = s + headB[CUT0];
    } else if (w == 2) {
        float s = warp_dot(score + (long long)row * DSC,
                           headW + (long long)(CUT0 + 1) * DIN, DIN, lane);
        if (lane == 0) g_gC1[row] = s + headB[CUT0 + 1];
    } else if (w == 3) {
        long long c = tv - CUT0; if (c < 0) c = 0; if (c > C0N - 1) c = C0N - 1;
        float s = warp_dot(h0 + (long long)row * K0,
                           t0b + c * K0, K0, lane);
        if (lane == 0) g_gT0[row] = s;
    } else {
        long long c = tv - CUT1; if (c < 0) c = 0; if (c > C1N - 1) c = C1N - 1;
        float s = warp_dot(h1t + (long long)row * K1,
                           t1b + c * K1, K1, lane);
        if (lane == 0) g_gT1[row] = s;
    }
}

// ---------------------------------------------------------------------------
// Combine: out[row] = selected log-prob
// ---------------------------------------------------------------------------
__global__ void combine_kernel(const void* __restrict__ t, float* __restrict__ out)
{
    int row = blockIdx.x * blockDim.x + threadIdx.x;
    if (row >= NROWS) return;

    float sh = 0.f;
    const float* hp = g_headPart + (long long)row * HEAD_TILES;
#pragma unroll 8
    for (int i = 0; i < HEAD_TILES; i++) sh += hp[i];

    float s0 = 0.f;
    const float* p0 = g_t0Part + (long long)row * T0_TILES;
    for (int i = 0; i < T0_TILES; i++) s0 += p0[i];

    float s1 = 0.f;
    const float* p1 = g_t1Part + (long long)row * T1_TILES;
    for (int i = 0; i < T1_TILES; i++) s1 += p1[i];

    float lseH = logf(sh);
    long long tv = load_t(t, row);
    float lp;
    if (tv < CUT0) {
        lp = g_gHT[row] - lseH;
    } else if (tv < CUT1) {
        lp = (g_gC0[row] - lseH) + (g_gT0[row] - logf(s0));
    } else {
        lp = (g_gC1[row] - lseH) + (g_gT1[row] - logf(s1));
    }
    out[row] = lp;
}

// ---------------------------------------------------------------------------
// Loss: -mean(out)
// ---------------------------------------------------------------------------
__global__ void loss_kernel(const float* __restrict__ out, float* __restrict__ loss)
{
    __shared__ float sm[1024];
    float s = 0.f;
    for (int i = threadIdx.x; i < NROWS; i += 1024) s += out[i];
    sm[threadIdx.x] = s;
    __syncthreads();
    for (int k = 512; k > 0; k >>= 1) {
        if (threadIdx.x < k) sm[threadIdx.x] += sm[threadIdx.x + k];
        __syncthreads();
    }
    if (threadIdx.x == 0) *loss = -sm[0] / (float)NROWS;
}

// ---------------------------------------------------------------------------
// Launcher
// ---------------------------------------------------------------------------
extern "C" void kernel_launch(void* const* d_in, const int* in_sizes, int n_in,
                              void* d_out, int out_size)
{
    const float* x     = (const float*)d_in[0];
    const void*  t     = d_in[1];
    const float* W1    = (const float*)d_in[2];
    const float* b1    = (const float*)d_in[3];
    const float* W2    = (const float*)d_in[4];
    const float* b2    = (const float*)d_in[5];
    const float* W3    = (const float*)d_in[6];
    const float* b3    = (const float*)d_in[7];
    const float* headW = (const float*)d_in[8];
    const float* headB = (const float*)d_in[9];
    const float* t0a   = (const float*)d_in[10];
    const float* t0b   = (const float*)d_in[11];
    const float* t1a   = (const float*)d_in[12];
    const float* t1b   = (const float*)d_in[13];
    float* out = (float*)d_out;

    float *h1, *h2, *score, *h0, *h1t, *hp, *p0, *p1;
    cudaGetSymbolAddress((void**)&h1,    g_h1);
    cudaGetSymbolAddress((void**)&h2,    g_h2);
    cudaGetSymbolAddress((void**)&score, g_score);
    cudaGetSymbolAddress((void**)&h0,    g_h0);
    cudaGetSymbolAddress((void**)&h1t,   g_h1t);
    cudaGetSymbolAddress((void**)&hp,    g_headPart);
    cudaGetSymbolAddress((void**)&p0,    g_t0Part);
    cudaGetSymbolAddress((void**)&p1,    g_t1Part);

    detect_t_kernel<<<1, 32>>>((const unsigned int*)t);

    dim3 blk(256);
    // MLP
    gemm_nt_kernel<true, true><<<dim3(H1DIM / 64, NROWS / 64), blk>>>(
        x, W1, b1, h1, NROWS, H1DIM, DIN);
    gemm_nt_kernel<true, true><<<dim3(H2DIM / 64 ? H2DIM / 64 : 1, NROWS / 64), blk>>>(
        h1, W2, b2, h2, NROWS, H2DIM, H1DIM);
    gemm_nt_kernel<true, true><<<dim3(DSC / 64, NROWS / 64), blk>>>(
        h2, W3, b3, score, NROWS, DSC, H2DIM);
    // Tail hidden projections (no bias, no relu)
    gemm_nt_kernel<false, false><<<dim3((K0 + 63) / 64, NROWS / 64), blk>>>(
        score, t0a, nullptr, h0, NROWS, K0, DSC);
    gemm_nt_kernel<false, false><<<dim3((K1 + 63) / 64, NROWS / 64), blk>>>(
        score, t1a, nullptr, h1t, NROWS, K1, DSC);
    // Fused sumexp partials
    sumexp_kernel<true><<<dim3(HEAD_TILES, NROWS / 64), blk>>>(
        score, headW, headB, hp, NROWS, HEADC, DSC, HEAD_TILES);
    sumexp_kernel<false><<<dim3(T0_TILES, NROWS / 64), blk>>>(
        h0, t0b, nullptr, p0, NROWS, C0N, K0, T0_TILES);
    sumexp_kernel<false><<<dim3(T1_TILES, NROWS / 64), blk>>>(
        h1t, t1b, nullptr, p1, NROWS, C1N, K1, T1_TILES);
    // Gathered logits
    gather_kernel<<<NROWS, 160>>>(score, h0, h1t, headW, headB, t0b, t1b, t);
    // Combine + loss
    combine_kernel<<<16, 256>>>(t, out);
    if (out_size > NROWS) {
        loss_kernel<<<1, 1024>>>(out, out + NROWS);
    }
}